// round 17
// baseline (speedup 1.0000x reference)
#include <cuda_runtime.h>
#include <cuda_fp16.h>
#include <cstdint>

#define NSITES   262144
#define CCH      64
#define BN_EPS_F 1e-3f
#define NTILES   2048        // 2048 tiles of 128 sites
#define GRIDC    296         // persistent conv CTAs (2 per SM x 148)
#define FEATBLK  (NSITES * 64 / 8 / 256)   // 8192 blocks for feature convert

// ---------------- scratch (__device__ globals; no allocations) ----------------
__device__ __align__(128) __half g_f16[NSITES * 64];          // features, fp16
__device__ __align__(128) __half g_w16[9 * 64 * 64];          // [k][cout][cin]
__device__ float g_psum[GRIDC * CCH];
__device__ float g_psq [GRIDC * CCH];
__device__ float g_scale[CCH];
__device__ float g_shift[CCH];

// ---------------- helpers ----------------
__device__ __forceinline__ uint32_t smem_u32(const void* p) {
    uint32_t a;
    asm("{ .reg .u64 t; cvta.to.shared.u64 t, %1; cvt.u32.u64 %0, t; }" : "=r"(a) : "l"(p));
    return a;
}
__device__ __forceinline__ void ldsm_x4(uint32_t& r0, uint32_t& r1, uint32_t& r2, uint32_t& r3,
                                        uint32_t addr) {
    asm volatile("ldmatrix.sync.aligned.m8n8.x4.shared.b16 {%0,%1,%2,%3}, [%4];"
                 : "=r"(r0), "=r"(r1), "=r"(r2), "=r"(r3) : "r"(addr));
}
__device__ __forceinline__ void mma_f16(float* d, const uint32_t* a, const uint32_t* b) {
    asm volatile(
        "mma.sync.aligned.m16n8k16.row.col.f32.f16.f16.f32 "
        "{%0,%1,%2,%3}, {%4,%5,%6,%7}, {%8,%9}, {%0,%1,%2,%3};"
        : "+f"(d[0]), "+f"(d[1]), "+f"(d[2]), "+f"(d[3])
        : "r"(a[0]), "r"(a[1]), "r"(a[2]), "r"(a[3]), "r"(b[0]), "r"(b[1]));
}
#define CP_ASYNC16(dst, src, sz) \
    asm volatile("cp.async.cg.shared.global [%0], [%1], 16, %2;" \
                 :: "r"(dst), "l"(src), "r"(sz) : "memory")
#define CP_COMMIT()  asm volatile("cp.async.commit_group;" ::: "memory")
#define CP_WAITG2()  asm volatile("cp.async.wait_group 2;" ::: "memory")

// ---------------- precompute: features -> fp16, weights -> fp16 [k][cout][cin] ----------------
__global__ __launch_bounds__(256) void split_all(const float* __restrict__ f,
                                                 const float* __restrict__ w)
{
    if (blockIdx.x < FEATBLK) {
        size_t i = ((size_t)blockIdx.x * 256 + threadIdx.x) * 8;
        float4 a = *(const float4*)(f + i);
        float4 b = *(const float4*)(f + i + 4);
        float v[8] = {a.x, a.y, a.z, a.w, b.x, b.y, b.z, b.w};
        __half h[8];
        #pragma unroll
        for (int j = 0; j < 8; ++j) h[j] = __float2half_rn(v[j]);
        *(uint4*)(g_f16 + i) = *(uint4*)h;
    } else {
        int i = (blockIdx.x - FEATBLK) * 256 + threadIdx.x;   // 0..36863
        if (i < 9 * 64 * 64) {
            int k = i >> 12, ci = (i >> 6) & 63, co = i & 63;
            g_w16[(k << 12) + (co << 6) + ci] = __float2half_rn(w[i]);
        }
    }
}

// ---------------- conv: persistent, 4-stage cp.async pipeline + fp16 HMMA ----------------
// Dynamic SMEM (96 KB): A stages 4 x 16384 @ 0 ; B stages 4 x 8192 @ 65536
#define STAGE_A   16384
#define OFF_B     65536
#define STAGE_B   8192
#define SMEM_CONV 98304

__global__ __launch_bounds__(256, 2) void conv_hmma(
    const int*   __restrict__ nbr,
    const float* __restrict__ bias,
    float*       __restrict__ out)
{
    extern __shared__ __align__(128) char smem[];
    const uint32_t sb = smem_u32(smem);

    const int tid  = threadIdx.x;
    const int wid  = tid >> 5;
    const int l    = tid & 31;
    const int WM   = wid >> 1;           // 0..3 : 32-row slice
    const int WN   = wid & 1;            // 0..1 : 32-col slice

    const int site = tid >> 1;           // 2 threads per site
    const int half = tid & 1;
    const int akey = site & 7;

    const int n_t = (NTILES - blockIdx.x + (GRIDC - 1)) / GRIDC;   // 6 or 7 tiles

    auto issue_A = [&](int row, int st) {
        uint32_t aD = sb + st * STAGE_A + (uint32_t)(site * 128);
        size_t r = (size_t)(row >= 0 ? row : 0);
        const char* src = (const char*)(g_f16 + r * 64 + half * 32);
        int sz = (row >= 0) ? 16 : 0;
        #pragma unroll
        for (int j = 0; j < 4; ++j) {
            int chunk = half * 4 + j;
            uint32_t sw = (uint32_t)((chunk ^ akey) * 16);
            CP_ASYNC16(aD + sw, src + j * 16, sz);
        }
    };
    auto issue_B = [&](int k, int st) {
        const char* wS = (const char*)(g_w16 + k * 4096);
        uint32_t bD = sb + OFF_B + st * STAGE_B;
        int e = tid * 2;
        #pragma unroll
        for (int j = 0; j < 2; ++j, ++e) {
            int r = e >> 3, chunk = e & 7;
            uint32_t sw = (uint32_t)(r * 128 + (chunk ^ (r & 7)) * 16);
            CP_ASYNC16(bD + sw, wS + e * 16, 16);
        }
    };

    // neighbor-index double buffer (current tile / next tile)
    int rows_cur[9], rows_next[9];
    {
        size_t p = (size_t)(blockIdx.x * 128 + site) * 9;
        #pragma unroll
        for (int k = 0; k < 9; ++k) rows_cur[k] = nbr[p + k];
    }

    // prologue: taps 0,1,2 of tile 0 in flight (stages 0,1,2)
    #pragma unroll
    for (int kk = 0; kk < 3; ++kk) {
        issue_A(rows_cur[kk], kk);
        issue_B(kk, kk);
        CP_COMMIT();
    }
    if (n_t > 1) {
        size_t p = (size_t)((blockIdx.x + GRIDC) * 128 + site) * 9;
        #pragma unroll
        for (int k = 0; k < 9; ++k) rows_next[k] = nbr[p + k];
    }

    float d[2][4][4];
    #pragma unroll
    for (int mt = 0; mt < 2; ++mt)
        #pragma unroll
        for (int nt = 0; nt < 4; ++nt)
            #pragma unroll
            for (int j = 0; j < 4; ++j) d[mt][nt][j] = 0.0f;

    // BN partials accumulated across ALL tiles of this CTA
    float colS[4][2] = {}, colQ[4][2] = {};

    const int aRow = l & 15;
    const int aCB  = (l >> 4) & 1;
    const int aKey = l & 7;
    uint32_t aOffRow[2];
    #pragma unroll
    for (int mt = 0; mt < 2; ++mt)
        aOffRow[mt] = (uint32_t)((WM * 32 + mt * 16 + aRow) * 128);
    const int bRowIn = ((l >> 4) & 1) * 8 + (l & 7);
    const int bCB    = (l >> 3) & 1;
    uint32_t bOffRow[2];
    #pragma unroll
    for (int p = 0; p < 2; ++p)
        bOffRow[p] = (uint32_t)((WN * 32 + p * 16 + bRowIn) * 128);

    int st   = 0;                         // stage of current tap (global tap % 4)
    int tile = blockIdx.x;
    for (int ti = 0; ti < n_t; ++ti, tile += GRIDC) {
        const int base = tile * 128;

        for (int k = 0; k < 9; ++k) {
            CP_WAITG2();                  // current tap resident (<=2 groups pending)
            __syncthreads();              // visible; issue-stage free (tap-1 consumers done)

            const int stIn = (st + 3) & 3;
            if (k < 6) {                  // lookahead within this tile
                issue_A(rows_cur[k + 3], stIn);
                issue_B(k + 3, stIn);
            } else if (ti + 1 < n_t) {    // lookahead into next tile (taps 0..2)
                issue_A(rows_next[k - 6], stIn);
                issue_B(k - 6, stIn);
            }
            CP_COMMIT();

            const uint32_t aBase = sb + (uint32_t)(st * STAGE_A);
            const uint32_t bBase = sb + OFF_B + (uint32_t)(st * STAGE_B);

            #pragma unroll
            for (int ks = 0; ks < 4; ++ks) {
                uint32_t a[2][4], bh[2][4];
                uint32_t swA = (uint32_t)(((ks * 2 + aCB) ^ aKey) << 4);
                uint32_t swB = (uint32_t)(((ks * 2 + bCB) ^ aKey) << 4);
                #pragma unroll
                for (int mt = 0; mt < 2; ++mt)
                    ldsm_x4(a[mt][0], a[mt][1], a[mt][2], a[mt][3],
                            aBase + aOffRow[mt] + swA);
                #pragma unroll
                for (int p = 0; p < 2; ++p)
                    ldsm_x4(bh[p][0], bh[p][1], bh[p][2], bh[p][3],
                            bBase + bOffRow[p] + swB);
                #pragma unroll
                for (int mt = 0; mt < 2; ++mt)
                    #pragma unroll
                    for (int p = 0; p < 2; ++p)
                        #pragma unroll
                        for (int q = 0; q < 2; ++q)
                            mma_f16(d[mt][p * 2 + q], a[mt], &bh[p][2 * q]);
            }

            st = (st + 1) & 3;
        }

        // ---- per-tile epilogue: bias add, store, BN accumulate, reset accum ----
        #pragma unroll
        for (int nt = 0; nt < 4; ++nt) {
            int col = WN * 32 + nt * 8 + 2 * (l & 3);
            float b0 = bias[col], b1 = bias[col + 1];
            #pragma unroll
            for (int mt = 0; mt < 2; ++mt) {
                int r0 = base + WM * 32 + mt * 16 + (l >> 2);
                float x0 = d[mt][nt][0] + b0, x1 = d[mt][nt][1] + b1;
                float x2 = d[mt][nt][2] + b0, x3 = d[mt][nt][3] + b1;
                *(float2*)(out + (size_t)r0 * 64 + col)       = make_float2(x0, x1);
                *(float2*)(out + (size_t)(r0 + 8) * 64 + col) = make_float2(x2, x3);
                colS[nt][0] += x0 + x2;  colQ[nt][0] += x0 * x0 + x2 * x2;
                colS[nt][1] += x1 + x3;  colQ[nt][1] += x1 * x1 + x3 * x3;
                d[mt][nt][0] = 0.f; d[mt][nt][1] = 0.f;
                d[mt][nt][2] = 0.f; d[mt][nt][3] = 0.f;
            }
        }

        // rotate index buffers; prefetch tile ti+2's indices
        #pragma unroll
        for (int k = 0; k < 9; ++k) rows_cur[k] = rows_next[k];
        if (ti + 2 < n_t) {
            size_t p = (size_t)((tile + 2 * GRIDC) * 128 + site) * 9;
            #pragma unroll
            for (int k = 0; k < 9; ++k) rows_next[k] = nbr[p + k];
        }
    }

    // ---- final BN partial reduce for this CTA ----
    #pragma unroll
    for (int off = 4; off <= 16; off <<= 1)
        #pragma unroll
        for (int nt = 0; nt < 4; ++nt)
            #pragma unroll
            for (int c = 0; c < 2; ++c) {
                colS[nt][c] += __shfl_xor_sync(0xffffffffu, colS[nt][c], off);
                colQ[nt][c] += __shfl_xor_sync(0xffffffffu, colQ[nt][c], off);
            }

    __syncthreads();                      // all warps done with all stages
    float* warpS = (float*)smem;          // [8][32]
    float* warpQ = (float*)(smem + 1024); // [8][32]
    if (l < 4) {
        #pragma unroll
        for (int nt = 0; nt < 4; ++nt) {
            warpS[wid * 32 + nt * 8 + 2 * l]     = colS[nt][0];
            warpS[wid * 32 + nt * 8 + 2 * l + 1] = colS[nt][1];
            warpQ[wid * 32 + nt * 8 + 2 * l]     = colQ[nt][0];
            warpQ[wid * 32 + nt * 8 + 2 * l + 1] = colQ[nt][1];
        }
    }
    __syncthreads();
    if (tid < 128) {
        int ch = tid & 63, kind = tid >> 6;
        int wn = ch >> 5, idx = ch & 31;
        const float* src = kind ? warpQ : warpS;
        float v = src[(0 * 2 + wn) * 32 + idx] + src[(1 * 2 + wn) * 32 + idx]
                + src[(2 * 2 + wn) * 32 + idx] + src[(3 * 2 + wn) * 32 + idx];
        if (kind) g_psq [blockIdx.x * 64 + ch] = v;
        else      g_psum[blockIdx.x * 64 + ch] = v;
    }
}

// ---------------- BN finalize: single block over 296 partials (deterministic) ----------------
__global__ __launch_bounds__(256) void bn_fin(const float* __restrict__ gamma,
                                              const float* __restrict__ beta)
{
    __shared__ float ss[4][64], sq[4][64];
    const int ch = threadIdx.x & 63;
    const int g  = threadIdx.x >> 6;
    float s = 0.f, q = 0.f;
    #pragma unroll 4
    for (int i = g; i < GRIDC; i += 4) {
        s += g_psum[i * 64 + ch];
        q += g_psq [i * 64 + ch];
    }
    ss[g][ch] = s; sq[g][ch] = q;
    __syncthreads();
    if (g == 0) {
        s = ss[0][ch] + ss[1][ch] + ss[2][ch] + ss[3][ch];
        q = sq[0][ch] + sq[1][ch] + sq[2][ch] + sq[3][ch];
        const float inv_n = 1.0f / (float)NSITES;
        float mean = s * inv_n;
        float var  = q * inv_n - mean * mean;
        float sc   = gamma[ch] * rsqrtf(var + BN_EPS_F);
        g_scale[ch] = sc;
        g_shift[ch] = beta[ch] - mean * sc;
    }
}

// ---------------- BN apply: 2 float4 per thread, streaming stores ----------------
__global__ __launch_bounds__(256) void bn_apply(const float* __restrict__ out,
                                                float* __restrict__ outbn)
{
    size_t i0 = ((size_t)blockIdx.x * 256 + threadIdx.x) * 2;
    #pragma unroll
    for (int j = 0; j < 2; ++j) {
        size_t i = i0 + j;
        float4 v = ((const float4*)out)[i];
        int cb = ((int)(i & 15)) * 4;
        float4 sc = *(const float4*)&g_scale[cb];
        float4 sh = *(const float4*)&g_shift[cb];
        float4 o = make_float4(v.x * sc.x + sh.x, v.y * sc.y + sh.y,
                               v.z * sc.z + sh.z, v.w * sc.w + sh.w);
        __stwt((float4*)outbn + i, o);
    }
}

// ---------------- launch ----------------
extern "C" void kernel_launch(void* const* d_in, const int* in_sizes, int n_in,
                              void* d_out, int out_size)
{
    const float* feat  = (const float*)d_in[0];
    const float* w     = (const float*)d_in[1];
    const float* bias  = (const float*)d_in[2];
    const float* gamma = (const float*)d_in[3];
    const float* beta  = (const float*)d_in[4];
    const int*   nbr   = (const int*)  d_in[5];

    float* out   = (float*)d_out;
    float* outbn = out + (size_t)NSITES * CCH;

    cudaFuncSetAttribute(conv_hmma, cudaFuncAttributeMaxDynamicSharedMemorySize, SMEM_CONV);

    split_all <<<FEATBLK + 144, 256>>>(feat, w);
    conv_hmma <<<GRIDC, 256, SMEM_CONV>>>(nbr, bias, out);
    bn_fin    <<<1, 256>>>(gamma, beta);
    bn_apply  <<<(NSITES * CCH / 8) / 256, 256>>>(out, outbn);
}